// round 4
// baseline (speedup 1.0000x reference)
#include <cuda_runtime.h>
#include <math.h>

#define Bn   8
#define Sn   1024
#define Dn   64
#define NHn  4
#define HEn  8            // 2*NH
#define BSn  (Bn*Sn)      // 8192
#define CW   (HEn*Dn)     // 512

// ---------------- scratch (no allocation allowed) ----------------
__device__ float g_qxp [Bn*Sn*Dn];
__device__ float g_kvxp[Bn*Sn*Dn];
__device__ float g_q   [Bn*HEn*Sn*Dn];   // (B,8,S,D)
__device__ float g_k   [Bn*HEn*Sn*Dn];
__device__ float g_v   [Bn*HEn*Sn*Dn];
__device__ float g_ctx [Bn*Sn*CW];       // (B,S,512)

// ---------------- helpers ----------------
__device__ __forceinline__ unsigned f2tf(float x) {
    unsigned r;
    asm("cvt.rna.tf32.f32 %0, %1;" : "=r"(r) : "f"(x));
    return r;
}

__device__ __forceinline__ void mma8(float* d, const unsigned* a, const unsigned* b) {
    asm volatile(
        "mma.sync.aligned.m16n8k8.row.col.f32.tf32.tf32.f32 "
        "{%0,%1,%2,%3}, {%4,%5,%6,%7}, {%8,%9}, {%0,%1,%2,%3};\n"
        : "+f"(d[0]), "+f"(d[1]), "+f"(d[2]), "+f"(d[3])
        : "r"(a[0]), "r"(a[1]), "r"(a[2]), "r"(a[3]), "r"(b[0]), "r"(b[1]));
}

// ---------------- 1) add positional table ----------------
__global__ void add_pos_kernel(const float* __restrict__ qx,
                               const float* __restrict__ kvx,
                               const float* __restrict__ pos) {
    int i = blockIdx.x * blockDim.x + threadIdx.x;
    if (i >= Bn*Sn*Dn) return;
    int sd = i % (Sn*Dn);
    float p = pos[sd];
    g_qxp[i]  = qx[i]  + p;
    g_kvxp[i] = kvx[i] + p;
}

// ---------------- 2) all projections in ONE launch ----------------
__global__ void proj_all_kernel(const float* __restrict__ Wq,  const float* __restrict__ bq,
                                const float* __restrict__ Wka, const float* __restrict__ bka,
                                const float* __restrict__ Wva, const float* __restrict__ bva,
                                const float* __restrict__ Wksa,const float* __restrict__ bksa,
                                const float* __restrict__ Wvsa,const float* __restrict__ bvsa) {
    int bx = blockIdx.x;
    const float *W, *bias, *x; float* dst; int N, n0, h0;
    if (bx < 8)       { W=Wq;   bias=bq;   x=g_qxp;  dst=g_q; N=512; n0=bx*64;      h0=0; }
    else if (bx < 12) { W=Wka;  bias=bka;  x=g_kvxp; dst=g_k; N=256; n0=(bx-8)*64;  h0=0; }
    else if (bx < 16) { W=Wksa; bias=bksa; x=g_qxp;  dst=g_k; N=256; n0=(bx-12)*64; h0=4; }
    else if (bx < 20) { W=Wva;  bias=bva;  x=g_kvxp; dst=g_v; N=256; n0=(bx-16)*64; h0=0; }
    else              { W=Wvsa; bias=bvsa; x=g_qxp;  dst=g_v; N=256; n0=(bx-20)*64; h0=4; }

    __shared__ float As[64][65];
    __shared__ float Ws[64][65];
    int tid = threadIdx.x;
    int tx = tid & 15, ty = tid >> 4;
    int m0 = blockIdx.y * 64;

    #pragma unroll
    for (int e = 0; e < 16; e++) {
        int idx = e * 256 + tid;
        int r = idx >> 6, c = idx & 63;
        As[r][c] = x[(m0 + r) * 64 + c];
        Ws[r][c] = W[r * N + n0 + c];
    }
    __syncthreads();

    float acc[4][4];
    #pragma unroll
    for (int ci = 0; ci < 4; ci++) {
        float bv = bias[n0 + tx + 16 * ci];
        #pragma unroll
        for (int ri = 0; ri < 4; ri++) acc[ri][ci] = bv;
    }
    #pragma unroll
    for (int k = 0; k < 64; k++) {
        float a[4], b2[4];
        #pragma unroll
        for (int ri = 0; ri < 4; ri++) a[ri]  = As[ty + 16 * ri][k];
        #pragma unroll
        for (int ci = 0; ci < 4; ci++) b2[ci] = Ws[k][tx + 16 * ci];
        #pragma unroll
        for (int ri = 0; ri < 4; ri++)
            #pragma unroll
            for (int ci = 0; ci < 4; ci++)
                acc[ri][ci] += a[ri] * b2[ci];
    }
    #pragma unroll
    for (int ri = 0; ri < 4; ri++)
        #pragma unroll
        for (int ci = 0; ci < 4; ci++) {
            int m = m0 + ty + 16 * ri;
            int n = n0 + tx + 16 * ci;
            int b = m >> 10, s = m & 1023;
            int h = n >> 6,  d = n & 63;
            dst[((size_t)(b * HEn + h0 + h) * Sn + s) * Dn + d] = acc[ri][ci];
        }
}

// ---------------- 3) FUSED scores -> softmax -> attn-write -> ctx ----------------
// One block = 32 query rows of one (b,h). Score strip 32x1024 lives in smem.
#define SCP 1025                       // padded row stride (floats)
__global__ void __launch_bounds__(256) fused_attn_kernel(float* __restrict__ attn) {
    extern __shared__ char smem[];
    float*    Sc = (float*)smem;                                // [32][1025] scores / P
    unsigned* KV = (unsigned*)(smem + 32 * SCP * sizeof(float)); // [128][65] tf32 tiles

    int bh = blockIdx.y;
    int m0 = blockIdx.x * 32;
    const float* qb = g_q + (size_t)bh * Sn * Dn;
    const float* kb = g_k + (size_t)bh * Sn * Dn;
    const float* vb = g_v + (size_t)bh * Sn * Dn;
    float* ab = attn + (size_t)bh * Sn * Sn;

    int tid = threadIdx.x, wid = tid >> 5, lane = tid & 31;
    int g = lane >> 2, tig = lane & 3;

    // ---- stage Q (32x64) as tf32 into KV buffer ----
    #pragma unroll
    for (int i = 0; i < 2; i++) {
        int lin = i * 256 + tid;          // 0..511
        int r = lin >> 4, c4 = lin & 15;
        float4 v = *(const float4*)&qb[(size_t)(m0 + r) * 64 + c4 * 4];
        unsigned* p = &KV[r * 65 + c4 * 4];
        p[0] = f2tf(v.x); p[1] = f2tf(v.y); p[2] = f2tf(v.z); p[3] = f2tf(v.w);
    }
    __syncthreads();

    // ---- preload Q fragments: aq[mt][ks][4] ----
    unsigned aq[2][8][4];
    #pragma unroll
    for (int mt = 0; mt < 2; mt++)
        #pragma unroll
        for (int ks = 0; ks < 8; ks++) {
            int r0 = mt * 16 + g, c0 = ks * 8 + tig;
            aq[mt][ks][0] = KV[r0 * 65 + c0];
            aq[mt][ks][1] = KV[(r0 + 8) * 65 + c0];
            aq[mt][ks][2] = KV[r0 * 65 + c0 + 4];
            aq[mt][ks][3] = KV[(r0 + 8) * 65 + c0 + 4];
        }
    __syncthreads();

    // ---- scores: loop K tiles of 128 rows, prefetch-to-regs double buffer ----
    float4 pre[8];
    #pragma unroll
    for (int i = 0; i < 8; i++) {
        int lin = i * 256 + tid;
        int r = lin >> 4, c4 = lin & 15;
        pre[i] = *(const float4*)&kb[(size_t)r * 64 + c4 * 4];
    }
    for (int kt = 0; kt < 8; kt++) {
        #pragma unroll
        for (int i = 0; i < 8; i++) {
            int lin = i * 256 + tid;
            int r = lin >> 4, c4 = lin & 15;
            unsigned* p = &KV[r * 65 + c4 * 4];
            p[0] = f2tf(pre[i].x); p[1] = f2tf(pre[i].y);
            p[2] = f2tf(pre[i].z); p[3] = f2tf(pre[i].w);
        }
        __syncthreads();
        if (kt < 7) {
            #pragma unroll
            for (int i = 0; i < 8; i++) {
                int lin = i * 256 + tid;
                int r = lin >> 4, c4 = lin & 15;
                pre[i] = *(const float4*)&kb[(size_t)((kt + 1) * 128 + r) * 64 + c4 * 4];
            }
        }
        #pragma unroll
        for (int nt2 = 0; nt2 < 2; nt2++) {
            int n0 = wid * 16 + nt2 * 8;
            float acc[2][4] = {};
            #pragma unroll
            for (int ks = 0; ks < 8; ks++) {
                unsigned bfr[2];
                bfr[0] = KV[(n0 + g) * 65 + ks * 8 + tig];
                bfr[1] = KV[(n0 + g) * 65 + ks * 8 + tig + 4];
                mma8(acc[0], aq[0][ks], bfr);
                mma8(acc[1], aq[1][ks], bfr);
            }
            #pragma unroll
            for (int mt = 0; mt < 2; mt++) {
                int row = mt * 16 + g;
                int col = kt * 128 + n0 + 2 * tig;
                Sc[row * SCP + col]           = acc[mt][0] * 0.125f;
                Sc[row * SCP + col + 1]       = acc[mt][1] * 0.125f;
                Sc[(row + 8) * SCP + col]     = acc[mt][2] * 0.125f;
                Sc[(row + 8) * SCP + col + 1] = acc[mt][3] * 0.125f;
            }
        }
        __syncthreads();
    }

    // ---- softmax in smem; write attn to gmem; store tf32 P back to smem ----
    {
        float vrow[32];
        #pragma unroll
        for (int rr = 0; rr < 4; rr++) {
            int row = wid * 4 + rr;
            float m = -1e30f;
            #pragma unroll
            for (int i = 0; i < 32; i++) {
                vrow[i] = Sc[row * SCP + lane + 32 * i];
                m = fmaxf(m, vrow[i]);
            }
            #pragma unroll
            for (int o = 16; o > 0; o >>= 1) m = fmaxf(m, __shfl_xor_sync(~0u, m, o));
            float s = 0.f;
            #pragma unroll
            for (int i = 0; i < 32; i++) { vrow[i] = __expf(vrow[i] - m); s += vrow[i]; }
            #pragma unroll
            for (int o = 16; o > 0; o >>= 1) s += __shfl_xor_sync(~0u, s, o);
            float inv = 1.0f / s;
            #pragma unroll
            for (int i = 0; i < 32; i++) {
                float a = vrow[i] * inv;
                Sc[row * SCP + lane + 32 * i] = __uint_as_float(f2tf(a));
                ab[(size_t)(m0 + row) * Sn + lane + 32 * i] = a;
            }
        }
    }
    __syncthreads();

    // ---- ctx = P @ V : loop V tiles of 128 rows ----
    float cacc[2][4] = {};
    #pragma unroll
    for (int i = 0; i < 8; i++) {
        int lin = i * 256 + tid;
        int r = lin >> 4, c4 = lin & 15;
        pre[i] = *(const float4*)&vb[(size_t)r * 64 + c4 * 4];
    }
    int n0c = wid * 8;
    for (int kt = 0; kt < 8; kt++) {
        #pragma unroll
        for (int i = 0; i < 8; i++) {
            int lin = i * 256 + tid;
            int r = lin >> 4, c4 = lin & 15;
            unsigned* p = &KV[r * 65 + c4 * 4];
            p[0] = f2tf(pre[i].x); p[1] = f2tf(pre[i].y);
            p[2] = f2tf(pre[i].z); p[3] = f2tf(pre[i].w);
        }
        __syncthreads();
        if (kt < 7) {
            #pragma unroll
            for (int i = 0; i < 8; i++) {
                int lin = i * 256 + tid;
                int r = lin >> 4, c4 = lin & 15;
                pre[i] = *(const float4*)&vb[(size_t)((kt + 1) * 128 + r) * 64 + c4 * 4];
            }
        }
        #pragma unroll
        for (int ks = 0; ks < 16; ks++) {
            int c0 = kt * 128 + ks * 8 + tig;
            unsigned bfr[2];
            bfr[0] = KV[(ks * 8 + tig) * 65 + n0c + g];
            bfr[1] = KV[(ks * 8 + tig + 4) * 65 + n0c + g];
            unsigned a0[4], a1[4];
            a0[0] = __float_as_uint(Sc[g * SCP + c0]);
            a0[1] = __float_as_uint(Sc[(g + 8) * SCP + c0]);
            a0[2] = __float_as_uint(Sc[g * SCP + c0 + 4]);
            a0[3] = __float_as_uint(Sc[(g + 8) * SCP + c0 + 4]);
            a1[0] = __float_as_uint(Sc[(16 + g) * SCP + c0]);
            a1[1] = __float_as_uint(Sc[(24 + g) * SCP + c0]);
            a1[2] = __float_as_uint(Sc[(16 + g) * SCP + c0 + 4]);
            a1[3] = __float_as_uint(Sc[(24 + g) * SCP + c0 + 4]);
            mma8(cacc[0], a0, bfr);
            mma8(cacc[1], a1, bfr);
        }
        __syncthreads();
    }

    // ---- write ctx (B,S,512) ----
    int b = bh >> 3, h = bh & 7;
    #pragma unroll
    for (int mt = 0; mt < 2; mt++) {
        int s = m0 + mt * 16 + g;
        int d = n0c + 2 * tig;
        *(float2*)&g_ctx[((size_t)(b * Sn + s)) * CW + h * 64 + d] =
            make_float2(cacc[mt][0], cacc[mt][1]);
        *(float2*)&g_ctx[((size_t)(b * Sn + s + 8)) * CW + h * 64 + d] =
            make_float2(cacc[mt][2], cacc[mt][3]);
    }
}
#define FUSED_SMEM (32 * SCP * 4 + 128 * 65 * 4)

// ---------------- 4) out = ctx @ Wo + bo ----------------
__global__ void outproj_kernel(const float* __restrict__ Wo,
                               const float* __restrict__ bo,
                               float* __restrict__ out) {
    __shared__ float As[64][17];
    __shared__ float Bs[16][65];
    int tid = threadIdx.x;
    int tx = tid & 15, ty = tid >> 4;
    int m0 = blockIdx.y * 64;

    float acc[4][4];
    #pragma unroll
    for (int ci = 0; ci < 4; ci++) {
        float bv = bo[tx + 16 * ci];
        #pragma unroll
        for (int ri = 0; ri < 4; ri++) acc[ri][ci] = bv;
    }
    for (int kt = 0; kt < CW; kt += 16) {
        #pragma unroll
        for (int e = 0; e < 4; e++) {
            int idx = e * 256 + tid;
            { int r = idx >> 4, c = idx & 15; As[r][c] = g_ctx[(size_t)(m0 + r) * CW + kt + c]; }
            { int r = idx >> 6, c = idx & 63; Bs[r][c] = Wo[(kt + r) * Dn + c]; }
        }
        __syncthreads();
        #pragma unroll
        for (int k = 0; k < 16; k++) {
            float a[4], b2[4];
            #pragma unroll
            for (int ri = 0; ri < 4; ri++) a[ri]  = As[ty + 16 * ri][k];
            #pragma unroll
            for (int ci = 0; ci < 4; ci++) b2[ci] = Bs[k][tx + 16 * ci];
            #pragma unroll
            for (int ri = 0; ri < 4; ri++)
                #pragma unroll
                for (int ci = 0; ci < 4; ci++)
                    acc[ri][ci] += a[ri] * b2[ci];
        }
        __syncthreads();
    }
    #pragma unroll
    for (int ri = 0; ri < 4; ri++)
        #pragma unroll
        for (int ci = 0; ci < 4; ci++)
            out[(size_t)(m0 + ty + 16 * ri) * Dn + tx + 16 * ci] = acc[ri][ci];
}

// ---------------- launch ----------------
extern "C" void kernel_launch(void* const* d_in, const int* in_sizes, int n_in,
                              void* d_out, int out_size) {
    const float* kvx  = (const float*)d_in[0];
    const float* qx   = (const float*)d_in[1];
    const float* pos  = (const float*)d_in[2];
    const float* Wq   = (const float*)d_in[3];
    const float* bq   = (const float*)d_in[4];
    const float* Wka  = (const float*)d_in[5];
    const float* bka  = (const float*)d_in[6];
    const float* Wva  = (const float*)d_in[7];
    const float* bva  = (const float*)d_in[8];
    const float* Wksa = (const float*)d_in[9];
    const float* bksa = (const float*)d_in[10];
    const float* Wvsa = (const float*)d_in[11];
    const float* bvsa = (const float*)d_in[12];
    const float* Wo   = (const float*)d_in[13];
    const float* bo   = (const float*)d_in[14];

    float* out  = (float*)d_out;
    float* attn = out + (size_t)Bn * Sn * Dn;

    static bool attr_set = false;
    if (!attr_set) {
        cudaFuncSetAttribute(fused_attn_kernel,
                             cudaFuncAttributeMaxDynamicSharedMemorySize, FUSED_SMEM);
        attr_set = true;
    }

    add_pos_kernel<<<(Bn*Sn*Dn + 255) / 256, 256>>>(qx, kvx, pos);
    proj_all_kernel<<<dim3(24, BSn/64), 256>>>(Wq, bq, Wka, bka, Wva, bva,
                                               Wksa, bksa, Wvsa, bvsa);
    fused_attn_kernel<<<dim3(Sn/32, Bn*HEn), 256, FUSED_SMEM>>>(attn);
    outproj_kernel<<<dim3(1, BSn/64), 256>>>(Wo, bo, out);
}

// round 5
// speedup vs baseline: 1.2318x; 1.2318x over previous
#include <cuda_runtime.h>
#include <math.h>

#define Bn   8
#define Sn   1024
#define Dn   64
#define NHn  4
#define HEn  8            // 2*NH
#define BSn  (Bn*Sn)      // 8192
#define CW   (HEn*Dn)     // 512

// ---------------- scratch (no allocation allowed) ----------------
__device__ float g_qxp [Bn*Sn*Dn];
__device__ float g_kvxp[Bn*Sn*Dn];
__device__ float g_q   [Bn*HEn*Sn*Dn];   // (B,8,S,D)
__device__ float g_k   [Bn*HEn*Sn*Dn];
__device__ float g_v   [Bn*HEn*Sn*Dn];
__device__ float g_ctx [Bn*Sn*CW];       // (B,S,512)

// ---------------- helpers ----------------
__device__ __forceinline__ unsigned f2tf(float x) {
    unsigned r;
    asm("cvt.rna.tf32.f32 %0, %1;" : "=r"(r) : "f"(x));
    return r;
}

__device__ __forceinline__ void mma8(float* d, const unsigned* a, const unsigned* b) {
    asm volatile(
        "mma.sync.aligned.m16n8k8.row.col.f32.tf32.tf32.f32 "
        "{%0,%1,%2,%3}, {%4,%5,%6,%7}, {%8,%9}, {%0,%1,%2,%3};\n"
        : "+f"(d[0]), "+f"(d[1]), "+f"(d[2]), "+f"(d[3])
        : "r"(a[0]), "r"(a[1]), "r"(a[2]), "r"(a[3]), "r"(b[0]), "r"(b[1]));
}

// ---------------- 1) add positional table ----------------
__global__ void add_pos_kernel(const float* __restrict__ qx,
                               const float* __restrict__ kvx,
                               const float* __restrict__ pos) {
    int i = blockIdx.x * blockDim.x + threadIdx.x;
    if (i >= Bn*Sn*Dn) return;
    int sd = i % (Sn*Dn);
    float p = pos[sd];
    g_qxp[i]  = qx[i]  + p;
    g_kvxp[i] = kvx[i] + p;
}

// ---------------- 2) all projections in ONE launch ----------------
__global__ void proj_all_kernel(const float* __restrict__ Wq,  const float* __restrict__ bq,
                                const float* __restrict__ Wka, const float* __restrict__ bka,
                                const float* __restrict__ Wva, const float* __restrict__ bva,
                                const float* __restrict__ Wksa,const float* __restrict__ bksa,
                                const float* __restrict__ Wvsa,const float* __restrict__ bvsa) {
    int bx = blockIdx.x;
    const float *W, *bias, *x; float* dst; int N, n0, h0;
    if (bx < 8)       { W=Wq;   bias=bq;   x=g_qxp;  dst=g_q; N=512; n0=bx*64;      h0=0; }
    else if (bx < 12) { W=Wka;  bias=bka;  x=g_kvxp; dst=g_k; N=256; n0=(bx-8)*64;  h0=0; }
    else if (bx < 16) { W=Wksa; bias=bksa; x=g_qxp;  dst=g_k; N=256; n0=(bx-12)*64; h0=4; }
    else if (bx < 20) { W=Wva;  bias=bva;  x=g_kvxp; dst=g_v; N=256; n0=(bx-16)*64; h0=0; }
    else              { W=Wvsa; bias=bvsa; x=g_qxp;  dst=g_v; N=256; n0=(bx-20)*64; h0=4; }

    __shared__ float As[64][65];
    __shared__ float Ws[64][65];
    int tid = threadIdx.x;
    int tx = tid & 15, ty = tid >> 4;
    int m0 = blockIdx.y * 64;

    #pragma unroll
    for (int e = 0; e < 16; e++) {
        int idx = e * 256 + tid;
        int r = idx >> 6, c = idx & 63;
        As[r][c] = x[(m0 + r) * 64 + c];
        Ws[r][c] = W[r * N + n0 + c];
    }
    __syncthreads();

    float acc[4][4];
    #pragma unroll
    for (int ci = 0; ci < 4; ci++) {
        float bv = bias[n0 + tx + 16 * ci];
        #pragma unroll
        for (int ri = 0; ri < 4; ri++) acc[ri][ci] = bv;
    }
    #pragma unroll
    for (int k = 0; k < 64; k++) {
        float a[4], b2[4];
        #pragma unroll
        for (int ri = 0; ri < 4; ri++) a[ri]  = As[ty + 16 * ri][k];
        #pragma unroll
        for (int ci = 0; ci < 4; ci++) b2[ci] = Ws[k][tx + 16 * ci];
        #pragma unroll
        for (int ri = 0; ri < 4; ri++)
            #pragma unroll
            for (int ci = 0; ci < 4; ci++)
                acc[ri][ci] += a[ri] * b2[ci];
    }
    #pragma unroll
    for (int ri = 0; ri < 4; ri++)
        #pragma unroll
        for (int ci = 0; ci < 4; ci++) {
            int m = m0 + ty + 16 * ri;
            int n = n0 + tx + 16 * ci;
            int b = m >> 10, s = m & 1023;
            int h = n >> 6,  d = n & 63;
            dst[((size_t)(b * HEn + h0 + h) * Sn + s) * Dn + d] = acc[ri][ci];
        }
}

// ---------------- 3) scores = (q @ k^T) * scale ----------------
// Register-direct tf32 mma: no smem. Block = 64 rows x 128 cols, 8 warps (2x4),
// warp tile 32x32. Fragments loaded straight from gmem (L1/L2-cached reuse).
__global__ void __launch_bounds__(256) scores_kernel(float* __restrict__ attn) {
    int bh = blockIdx.z;
    const float* __restrict__ qb = g_q + (size_t)bh * Sn * Dn;
    const float* __restrict__ kb = g_k + (size_t)bh * Sn * Dn;
    float* cb = attn + (size_t)bh * Sn * Sn;

    int tid = threadIdx.x, wid = tid >> 5, lane = tid & 31;
    int wm = wid >> 2, wn = wid & 3;
    int g = lane >> 2, tig = lane & 3;
    int m0 = blockIdx.y * 64 + wm * 32;
    int n0 = blockIdx.x * 128 + wn * 32;

    float acc[2][4][4] = {};
    #pragma unroll
    for (int ks = 0; ks < 8; ks++) {
        int c = ks * 8 + tig;
        unsigned a[2][4];
        #pragma unroll
        for (int mt = 0; mt < 2; mt++) {
            const float* q0 = qb + (size_t)(m0 + mt * 16 + g) * 64 + c;
            a[mt][0] = f2tf(q0[0]);
            a[mt][1] = f2tf(q0[8 * 64]);
            a[mt][2] = f2tf(q0[4]);
            a[mt][3] = f2tf(q0[8 * 64 + 4]);
        }
        #pragma unroll
        for (int j = 0; j < 4; j++) {
            const float* k0 = kb + (size_t)(n0 + j * 8 + g) * 64 + c;
            unsigned b2[2];
            b2[0] = f2tf(k0[0]);
            b2[1] = f2tf(k0[4]);
            mma8(acc[0][j], a[0], b2);
            mma8(acc[1][j], a[1], b2);
        }
    }
    #pragma unroll
    for (int mt = 0; mt < 2; mt++)
        #pragma unroll
        for (int j = 0; j < 4; j++) {
            int row = m0 + mt * 16 + g;
            int col = n0 + j * 8 + 2 * tig;
            *(float2*)&cb[(size_t)row * Sn + col] =
                make_float2(acc[mt][j][0] * 0.125f, acc[mt][j][1] * 0.125f);
            *(float2*)&cb[(size_t)(row + 8) * Sn + col] =
                make_float2(acc[mt][j][2] * 0.125f, acc[mt][j][3] * 0.125f);
        }
}

// ---------------- 4) softmax over rows of length 1024 ----------------
__global__ void softmax_kernel(float* __restrict__ attn) {
    float* p = attn + (size_t)blockIdx.x * Sn;
    int t = threadIdx.x;  // 256
    __shared__ float sm[8], ss[8];

    float4 v = ((float4*)p)[t];
    float m = fmaxf(fmaxf(v.x, v.y), fmaxf(v.z, v.w));
    #pragma unroll
    for (int o = 16; o > 0; o >>= 1) m = fmaxf(m, __shfl_xor_sync(~0u, m, o));
    if ((t & 31) == 0) sm[t >> 5] = m;
    __syncthreads();
    m = sm[0];
    #pragma unroll
    for (int w = 1; w < 8; w++) m = fmaxf(m, sm[w]);

    v.x = __expf(v.x - m); v.y = __expf(v.y - m);
    v.z = __expf(v.z - m); v.w = __expf(v.w - m);
    float sum = v.x + v.y + v.z + v.w;
    #pragma unroll
    for (int o = 16; o > 0; o >>= 1) sum += __shfl_xor_sync(~0u, sum, o);
    if ((t & 31) == 0) ss[t >> 5] = sum;
    __syncthreads();
    sum = 0.f;
    #pragma unroll
    for (int w = 0; w < 8; w++) sum += ss[w];
    float inv = 1.0f / sum;

    v.x *= inv; v.y *= inv; v.z *= inv; v.w *= inv;
    ((float4*)p)[t] = v;
}

// ---------------- 5) ctx = attn @ v ----------------
// Block = 256 rows x 64 cols, 8 warps (warp = 32 rows x 64 cols).
// V chunk (128 k-rows) staged in conflict-free smem (stride 72: bank = 8*tig+g).
// P fragments loaded register-direct from gmem.
__global__ void __launch_bounds__(256) ctx_kernel(const float* __restrict__ attn) {
    __shared__ unsigned Vs[128][72];
    int bh = blockIdx.y;
    int b = bh >> 3, h = bh & 7;
    const float* __restrict__ ab = attn + (size_t)bh * Sn * Sn;
    const float* __restrict__ vb = g_v + (size_t)bh * Sn * Dn;

    int tid = threadIdx.x, wid = tid >> 5, lane = tid & 31;
    int g = lane >> 2, tig = lane & 3;
    int r0 = blockIdx.x * 256 + wid * 32;

    float acc[2][8][4] = {};
    for (int kt = 0; kt < 8; kt++) {
        #pragma unroll
        for (int e = 0; e < 8; e++) {
            int lin = e * 256 + tid;
            int r = lin >> 4, c4 = lin & 15;
            float4 v = *(const float4*)&vb[(size_t)(kt * 128 + r) * 64 + c4 * 4];
            uint4 t;
            t.x = f2tf(v.x); t.y = f2tf(v.y); t.z = f2tf(v.z); t.w = f2tf(v.w);
            *(uint4*)&Vs[r][c4 * 4] = t;
        }
        __syncthreads();
        #pragma unroll
        for (int ks = 0; ks < 16; ks++) {
            int c = kt * 128 + ks * 8 + tig;
            unsigned a[2][4];
            #pragma unroll
            for (int mt = 0; mt < 2; mt++) {
                const float* p0 = ab + (size_t)(r0 + mt * 16 + g) * Sn + c;
                a[mt][0] = f2tf(p0[0]);
                a[mt][1] = f2tf(p0[8 * Sn]);
                a[mt][2] = f2tf(p0[4]);
                a[mt][3] = f2tf(p0[8 * Sn + 4]);
            }
            #pragma unroll
            for (int j = 0; j < 8; j++) {
                unsigned b2[2];
                b2[0] = Vs[ks * 8 + tig][j * 8 + g];
                b2[1] = Vs[ks * 8 + tig + 4][j * 8 + g];
                mma8(acc[0][j], a[0], b2);
                mma8(acc[1][j], a[1], b2);
            }
        }
        __syncthreads();
    }
    #pragma unroll
    for (int mt = 0; mt < 2; mt++)
        #pragma unroll
        for (int j = 0; j < 8; j++) {
            int s = r0 + mt * 16 + g;
            int d = j * 8 + 2 * tig;
            *(float2*)&g_ctx[((size_t)(b * Sn + s)) * CW + h * 64 + d] =
                make_float2(acc[mt][j][0], acc[mt][j][1]);
            *(float2*)&g_ctx[((size_t)(b * Sn + s + 8)) * CW + h * 64 + d] =
                make_float2(acc[mt][j][2], acc[mt][j][3]);
        }
}

// ---------------- 6) out = ctx @ Wo + bo ----------------
// 16-row tiles -> 512 blocks (grid no longer starves SMs).
__global__ void __launch_bounds__(256) outproj_kernel(const float* __restrict__ Wo,
                                                      const float* __restrict__ bo,
                                                      float* __restrict__ out) {
    __shared__ float As[16][36];
    __shared__ float Bs[32][68];
    int tid = threadIdx.x;
    int ty = tid >> 4, tx = tid & 15;
    int m0 = blockIdx.x * 16;

    float acc[4];
    #pragma unroll
    for (int c2 = 0; c2 < 4; c2++) acc[c2] = bo[tx * 4 + c2];

    for (int kt = 0; kt < CW; kt += 32) {
        {
            int r = tid >> 4, c = (tid & 15) * 2;
            *(float2*)&As[r][c] = *(const float2*)&g_ctx[(size_t)(m0 + r) * CW + kt + c];
        }
        #pragma unroll
        for (int e = 0; e < 2; e++) {
            int lin = e * 256 + tid;
            int r = lin >> 4, c4 = lin & 15;
            *(float4*)&Bs[r][c4 * 4] = *(const float4*)&Wo[(size_t)(kt + r) * 64 + c4 * 4];
        }
        __syncthreads();
        #pragma unroll
        for (int k = 0; k < 32; k++) {
            float a = As[ty][k];
            float4 bv = *(const float4*)&Bs[k][tx * 4];
            acc[0] += a * bv.x; acc[1] += a * bv.y;
            acc[2] += a * bv.z; acc[3] += a * bv.w;
        }
        __syncthreads();
    }
    float4 r4 = make_float4(acc[0], acc[1], acc[2], acc[3]);
    *(float4*)&out[(size_t)(m0 + ty) * 64 + tx * 4] = r4;
}

// ---------------- launch ----------------
extern "C" void kernel_launch(void* const* d_in, const int* in_sizes, int n_in,
                              void* d_out, int out_size) {
    const float* kvx  = (const float*)d_in[0];
    const float* qx   = (const float*)d_in[1];
    const float* pos  = (const float*)d_in[2];
    const float* Wq   = (const float*)d_in[3];
    const float* bq   = (const float*)d_in[4];
    const float* Wka  = (const float*)d_in[5];
    const float* bka  = (const float*)d_in[6];
    const float* Wva  = (const float*)d_in[7];
    const float* bva  = (const float*)d_in[8];
    const float* Wksa = (const float*)d_in[9];
    const float* bksa = (const float*)d_in[10];
    const float* Wvsa = (const float*)d_in[11];
    const float* bvsa = (const float*)d_in[12];
    const float* Wo   = (const float*)d_in[13];
    const float* bo   = (const float*)d_in[14];

    float* out  = (float*)d_out;
    float* attn = out + (size_t)Bn * Sn * Dn;

    add_pos_kernel<<<(Bn*Sn*Dn + 255) / 256, 256>>>(qx, kvx, pos);
    proj_all_kernel<<<dim3(24, BSn/64), 256>>>(Wq, bq, Wka, bka, Wva, bva,
                                               Wksa, bksa, Wvsa, bvsa);
    scores_kernel <<<dim3(Sn/128, Sn/64, Bn*HEn), 256>>>(attn);
    softmax_kernel<<<Bn*HEn*Sn, 256>>>(attn);
    ctx_kernel    <<<dim3(Sn/256, Bn*HEn), 256>>>(attn);
    outproj_kernel<<<BSn/16, 256>>>(Wo, bo, out);
}

// round 6
// speedup vs baseline: 1.6443x; 1.3349x over previous
#include <cuda_runtime.h>
#include <math.h>

#define Bn   8
#define Sn   1024
#define Dn   64
#define NHn  4
#define HEn  8            // 2*NH
#define BSn  (Bn*Sn)      // 8192
#define CW   (HEn*Dn)     // 512

// ---------------- scratch (no allocation allowed) ----------------
__device__ float g_q   [Bn*HEn*Sn*Dn];   // (B,8,S,D)  tf32-rounded
__device__ float g_k   [Bn*HEn*Sn*Dn];   // tf32-rounded
__device__ float g_v   [Bn*HEn*Sn*Dn];   // tf32-rounded
__device__ float g_ctx [Bn*Sn*CW];       // (B,S,512)

// ---------------- helpers ----------------
__device__ __forceinline__ unsigned f2tf(float x) {
    unsigned r;
    asm("cvt.rna.tf32.f32 %0, %1;" : "=r"(r) : "f"(x));
    return r;
}

__device__ __forceinline__ void mma8(float* d, const unsigned* a, const unsigned* b) {
    asm volatile(
        "mma.sync.aligned.m16n8k8.row.col.f32.tf32.tf32.f32 "
        "{%0,%1,%2,%3}, {%4,%5,%6,%7}, {%8,%9}, {%0,%1,%2,%3};\n"
        : "+f"(d[0]), "+f"(d[1]), "+f"(d[2]), "+f"(d[3])
        : "r"(a[0]), "r"(a[1]), "r"(a[2]), "r"(a[3]), "r"(b[0]), "r"(b[1]));
}

// ---------------- 1) all projections (pos-add fused), ONE launch ----------------
__global__ void proj_all_kernel(const float* __restrict__ qx, const float* __restrict__ kvx,
                                const float* __restrict__ pos,
                                const float* __restrict__ Wq,  const float* __restrict__ bq,
                                const float* __restrict__ Wka, const float* __restrict__ bka,
                                const float* __restrict__ Wva, const float* __restrict__ bva,
                                const float* __restrict__ Wksa,const float* __restrict__ bksa,
                                const float* __restrict__ Wvsa,const float* __restrict__ bvsa) {
    int bx = blockIdx.x;
    const float *W, *bias, *x; float* dst; int N, n0, h0;
    if (bx < 8)       { W=Wq;   bias=bq;   x=qx;  dst=g_q; N=512; n0=bx*64;      h0=0; }
    else if (bx < 12) { W=Wka;  bias=bka;  x=kvx; dst=g_k; N=256; n0=(bx-8)*64;  h0=0; }
    else if (bx < 16) { W=Wksa; bias=bksa; x=qx;  dst=g_k; N=256; n0=(bx-12)*64; h0=4; }
    else if (bx < 20) { W=Wva;  bias=bva;  x=kvx; dst=g_v; N=256; n0=(bx-16)*64; h0=0; }
    else              { W=Wvsa; bias=bvsa; x=qx;  dst=g_v; N=256; n0=(bx-20)*64; h0=4; }

    __shared__ float As[64][65];
    __shared__ float Ws[64][65];
    int tid = threadIdx.x;
    int tx = tid & 15, ty = tid >> 4;
    int m0 = blockIdx.y * 64;

    #pragma unroll
    for (int e = 0; e < 16; e++) {
        int idx = e * 256 + tid;
        int r = idx >> 6, c = idx & 63;
        int s = (m0 + r) & 1023;
        As[r][c] = x[(size_t)(m0 + r) * 64 + c] + pos[s * 64 + c];
        Ws[r][c] = W[r * N + n0 + c];
    }
    __syncthreads();

    float acc[4][4];
    #pragma unroll
    for (int ci = 0; ci < 4; ci++) {
        float bv = bias[n0 + tx + 16 * ci];
        #pragma unroll
        for (int ri = 0; ri < 4; ri++) acc[ri][ci] = bv;
    }
    #pragma unroll
    for (int k = 0; k < 64; k++) {
        float a[4], b2[4];
        #pragma unroll
        for (int ri = 0; ri < 4; ri++) a[ri]  = As[ty + 16 * ri][k];
        #pragma unroll
        for (int ci = 0; ci < 4; ci++) b2[ci] = Ws[k][tx + 16 * ci];
        #pragma unroll
        for (int ri = 0; ri < 4; ri++)
            #pragma unroll
            for (int ci = 0; ci < 4; ci++)
                acc[ri][ci] += a[ri] * b2[ci];
    }
    #pragma unroll
    for (int ri = 0; ri < 4; ri++)
        #pragma unroll
        for (int ci = 0; ci < 4; ci++) {
            int m = m0 + ty + 16 * ri;
            int n = n0 + tx + 16 * ci;
            int b = m >> 10, s = m & 1023;
            int h = n >> 6,  d = n & 63;
            // pre-round to tf32 so consumers skip all cvt
            dst[((size_t)(b * HEn + h0 + h) * Sn + s) * Dn + d] =
                __uint_as_float(f2tf(acc[ri][ci]));
        }
}

// ---------------- 2) scores = (q @ k^T) * scale ----------------
// Block 64m x 128n, 8 warps (2x4), warp tile 32x32.
// Coalesced float4 staging into smem (stride 72 = conflict-free fragments).
__global__ void __launch_bounds__(256) scores_kernel(float* __restrict__ attn) {
    extern __shared__ unsigned sh[];
    unsigned* Qs = sh;            // [64][72]
    unsigned* Ks = sh + 64 * 72;  // [128][72]

    int bh = blockIdx.z;
    const float* __restrict__ qb = g_q + (size_t)bh * Sn * Dn;
    const float* __restrict__ kb = g_k + (size_t)bh * Sn * Dn;
    float* cb = attn + (size_t)bh * Sn * Sn;

    int tid = threadIdx.x, wid = tid >> 5, lane = tid & 31;
    int wm = wid >> 2, wn = wid & 3;
    int g = lane >> 2, tig = lane & 3;
    int m0 = blockIdx.y * 64, n0 = blockIdx.x * 128;

    #pragma unroll
    for (int e = 0; e < 4; e++) {
        int lin = e * 256 + tid;
        int r = lin >> 4, c4 = lin & 15;
        *(uint4*)&Qs[r * 72 + c4 * 4] = *(const uint4*)&qb[(size_t)(m0 + r) * 64 + c4 * 4];
    }
    #pragma unroll
    for (int e = 0; e < 8; e++) {
        int lin = e * 256 + tid;
        int r = lin >> 4, c4 = lin & 15;
        *(uint4*)&Ks[r * 72 + c4 * 4] = *(const uint4*)&kb[(size_t)(n0 + r) * 64 + c4 * 4];
    }
    __syncthreads();

    float acc[2][4][4] = {};
    int ar0 = (wm * 32 + g) * 72;
    #pragma unroll
    for (int ks = 0; ks < 8; ks++) {
        int c = ks * 8 + tig;
        unsigned a0[4], a1[4];
        a0[0] = Qs[ar0 + c];            a0[1] = Qs[ar0 + 8 * 72 + c];
        a0[2] = Qs[ar0 + c + 4];        a0[3] = Qs[ar0 + 8 * 72 + c + 4];
        a1[0] = Qs[ar0 + 16 * 72 + c];  a1[1] = Qs[ar0 + 24 * 72 + c];
        a1[2] = Qs[ar0 + 16 * 72 + c + 4]; a1[3] = Qs[ar0 + 24 * 72 + c + 4];
        #pragma unroll
        for (int j = 0; j < 4; j++) {
            int br = (wn * 32 + j * 8 + g) * 72;
            unsigned b2[2] = { Ks[br + c], Ks[br + c + 4] };
            mma8(acc[0][j], a0, b2);
            mma8(acc[1][j], a1, b2);
        }
    }
    #pragma unroll
    for (int mt = 0; mt < 2; mt++)
        #pragma unroll
        for (int j = 0; j < 4; j++) {
            int row = m0 + wm * 32 + mt * 16 + g;
            int col = n0 + wn * 32 + j * 8 + 2 * tig;
            *(float2*)&cb[(size_t)row * Sn + col] =
                make_float2(acc[mt][j][0] * 0.125f, acc[mt][j][1] * 0.125f);
            *(float2*)&cb[(size_t)(row + 8) * Sn + col] =
                make_float2(acc[mt][j][2] * 0.125f, acc[mt][j][3] * 0.125f);
        }
}
#define SCORES_SMEM ((64 + 128) * 72 * 4)

// ---------------- 3) softmax over rows of length 1024 ----------------
__global__ void softmax_kernel(float* __restrict__ attn) {
    float* p = attn + (size_t)blockIdx.x * Sn;
    int t = threadIdx.x;  // 256
    __shared__ float sm[8], ss[8];

    float4 v = ((float4*)p)[t];
    float m = fmaxf(fmaxf(v.x, v.y), fmaxf(v.z, v.w));
    #pragma unroll
    for (int o = 16; o > 0; o >>= 1) m = fmaxf(m, __shfl_xor_sync(~0u, m, o));
    if ((t & 31) == 0) sm[t >> 5] = m;
    __syncthreads();
    m = sm[0];
    #pragma unroll
    for (int w = 1; w < 8; w++) m = fmaxf(m, sm[w]);

    v.x = __expf(v.x - m); v.y = __expf(v.y - m);
    v.z = __expf(v.z - m); v.w = __expf(v.w - m);
    float sum = v.x + v.y + v.z + v.w;
    #pragma unroll
    for (int o = 16; o > 0; o >>= 1) sum += __shfl_xor_sync(~0u, sum, o);
    if ((t & 31) == 0) ss[t >> 5] = sum;
    __syncthreads();
    sum = 0.f;
    #pragma unroll
    for (int w = 0; w < 8; w++) sum += ss[w];
    float inv = 1.0f / sum;

    v.x *= inv; v.y *= inv; v.z *= inv; v.w *= inv;
    ((float4*)p)[t] = v;
}

// ---------------- 4) ctx = attn @ v ----------------
// Block 128m x 64n, 8 warps (4x2), warp tile 32x32. K chunks of 64.
// P staged with cvt during STS; V pre-rounded (raw copy).
__global__ void __launch_bounds__(256) ctx_kernel(const float* __restrict__ attn) {
    extern __shared__ unsigned sh[];
    unsigned* Ps = sh;             // [128][72]
    unsigned* Vs = sh + 128 * 72;  // [64][72]

    int bh = blockIdx.y;
    int b = bh >> 3, h = bh & 7;
    const float* __restrict__ ab = attn + (size_t)bh * Sn * Sn;
    const float* __restrict__ vb = g_v + (size_t)bh * Sn * Dn;

    int tid = threadIdx.x, wid = tid >> 5, lane = tid & 31;
    int wm = wid >> 1, wn = wid & 1;
    int g = lane >> 2, tig = lane & 3;
    int rblk = blockIdx.x * 128;

    float acc[2][4][4] = {};
    for (int kt = 0; kt < 16; kt++) {
        #pragma unroll
        for (int e = 0; e < 8; e++) {
            int lin = e * 256 + tid;
            int r = lin >> 4, c4 = lin & 15;
            float4 v = *(const float4*)&ab[(size_t)(rblk + r) * Sn + kt * 64 + c4 * 4];
            uint4 t;
            t.x = f2tf(v.x); t.y = f2tf(v.y); t.z = f2tf(v.z); t.w = f2tf(v.w);
            *(uint4*)&Ps[r * 72 + c4 * 4] = t;
        }
        #pragma unroll
        for (int e = 0; e < 4; e++) {
            int lin = e * 256 + tid;
            int r = lin >> 4, c4 = lin & 15;
            *(uint4*)&Vs[r * 72 + c4 * 4] =
                *(const uint4*)&vb[(size_t)(kt * 64 + r) * 64 + c4 * 4];
        }
        __syncthreads();

        int ar0 = (wm * 32 + g) * 72;
        #pragma unroll
        for (int ks = 0; ks < 8; ks++) {
            int c = ks * 8 + tig;
            unsigned a0[4], a1[4];
            a0[0] = Ps[ar0 + c];            a0[1] = Ps[ar0 + 8 * 72 + c];
            a0[2] = Ps[ar0 + c + 4];        a0[3] = Ps[ar0 + 8 * 72 + c + 4];
            a1[0] = Ps[ar0 + 16 * 72 + c];  a1[1] = Ps[ar0 + 24 * 72 + c];
            a1[2] = Ps[ar0 + 16 * 72 + c + 4]; a1[3] = Ps[ar0 + 24 * 72 + c + 4];
            #pragma unroll
            for (int j = 0; j < 4; j++) {
                int nn = wn * 32 + j * 8 + g;
                unsigned b2[2] = { Vs[c * 72 + nn], Vs[(c + 4) * 72 + nn] };
                mma8(acc[0][j], a0, b2);
                mma8(acc[1][j], a1, b2);
            }
        }
        __syncthreads();
    }

    #pragma unroll
    for (int mt = 0; mt < 2; mt++)
        #pragma unroll
        for (int j = 0; j < 4; j++) {
            int s = rblk + wm * 32 + mt * 16 + g;
            int d = wn * 32 + j * 8 + 2 * tig;
            *(float2*)&g_ctx[((size_t)(b * Sn + s)) * CW + h * 64 + d] =
                make_float2(acc[mt][j][0], acc[mt][j][1]);
            *(float2*)&g_ctx[((size_t)(b * Sn + s + 8)) * CW + h * 64 + d] =
                make_float2(acc[mt][j][2], acc[mt][j][3]);
        }
}
#define CTX_SMEM ((128 + 64) * 72 * 4)

// ---------------- 5) out = ctx @ Wo + bo ----------------
__global__ void __launch_bounds__(256) outproj_kernel(const float* __restrict__ Wo,
                                                      const float* __restrict__ bo,
                                                      float* __restrict__ out) {
    __shared__ float As[16][36];
    __shared__ float Bs[32][68];
    int tid = threadIdx.x;
    int ty = tid >> 4, tx = tid & 15;
    int m0 = blockIdx.x * 16;

    float acc[4];
    #pragma unroll
    for (int c2 = 0; c2 < 4; c2++) acc[c2] = bo[tx * 4 + c2];

    for (int kt = 0; kt < CW; kt += 32) {
        {
            int r = tid >> 4, c = (tid & 15) * 2;
            *(float2*)&As[r][c] = *(const float2*)&g_ctx[(size_t)(m0 + r) * CW + kt + c];
        }
        #pragma unroll
        for (int e = 0; e < 2; e++) {
            int lin = e * 256 + tid;
            int r = lin >> 4, c4 = lin & 15;
            *(float4*)&Bs[r][c4 * 4] = *(const float4*)&Wo[(size_t)(kt + r) * 64 + c4 * 4];
        }
        __syncthreads();
        #pragma unroll
        for (int k = 0; k < 32; k++) {
            float a = As[ty][k];
            float4 bv = *(const float4*)&Bs[k][tx * 4];
            acc[0] += a * bv.x; acc[1] += a * bv.y;
            acc[2] += a * bv.z; acc[3] += a * bv.w;
        }
        __syncthreads();
    }
    *(float4*)&out[(size_t)(m0 + ty) * 64 + tx * 4] =
        make_float4(acc[0], acc[1], acc[2], acc[3]);
}

// ---------------- launch ----------------
extern "C" void kernel_launch(void* const* d_in, const int* in_sizes, int n_in,
                              void* d_out, int out_size) {
    const float* kvx  = (const float*)d_in[0];
    const float* qx   = (const float*)d_in[1];
    const float* pos  = (const float*)d_in[2];
    const float* Wq   = (const float*)d_in[3];
    const float* bq   = (const float*)d_in[4];
    const float* Wka  = (const float*)d_in[5];
    const float* bka  = (const float*)d_in[6];
    const float* Wva  = (const float*)d_in[7];
    const float* bva  = (const float*)d_in[8];
    const float* Wksa = (const float*)d_in[9];
    const float* bksa = (const float*)d_in[10];
    const float* Wvsa = (const float*)d_in[11];
    const float* bvsa = (const float*)d_in[12];
    const float* Wo   = (const float*)d_in[13];
    const float* bo   = (const float*)d_in[14];

    float* out  = (float*)d_out;
    float* attn = out + (size_t)Bn * Sn * Dn;

    static bool attr_set = false;
    if (!attr_set) {
        cudaFuncSetAttribute(scores_kernel,
                             cudaFuncAttributeMaxDynamicSharedMemorySize, SCORES_SMEM);
        cudaFuncSetAttribute(ctx_kernel,
                             cudaFuncAttributeMaxDynamicSharedMemorySize, CTX_SMEM);
        attr_set = true;
    }

    proj_all_kernel<<<dim3(24, BSn/64), 256>>>(qx, kvx, pos, Wq, bq, Wka, bka,
                                               Wva, bva, Wksa, bksa, Wvsa, bvsa);
    scores_kernel <<<dim3(Sn/128, Sn/64, Bn*HEn), 256, SCORES_SMEM>>>(attn);
    softmax_kernel<<<Bn*HEn*Sn, 256>>>(attn);
    ctx_kernel    <<<dim3(Sn/128, Bn*HEn), 256, CTX_SMEM>>>(attn);
    outproj_kernel<<<BSn/16, 256>>>(Wo, bo, out);
}

// round 7
// speedup vs baseline: 1.6904x; 1.0280x over previous
#include <cuda_runtime.h>
#include <math.h>

#define Bn   8
#define Sn   1024
#define Dn   64
#define NHn  4
#define HEn  8            // 2*NH
#define BSn  (Bn*Sn)      // 8192
#define CW   (HEn*Dn)     // 512

// ---------------- scratch (no allocation allowed) ----------------
__device__ float g_q   [Bn*HEn*Sn*Dn];   // (B,8,S,D)  tf32-rounded, pre-scaled by 1/8
__device__ float g_k   [Bn*HEn*Sn*Dn];   // tf32-rounded
__device__ float g_v   [Bn*HEn*Sn*Dn];   // tf32-rounded
__device__ float g_ctx [Bn*Sn*CW];       // (B,S,512)

// ---------------- helpers ----------------
__device__ __forceinline__ unsigned f2tf(float x) {
    unsigned r;
    asm("cvt.rna.tf32.f32 %0, %1;" : "=r"(r) : "f"(x));
    return r;
}

__device__ __forceinline__ void mma8(float* d, const unsigned* a, const unsigned* b) {
    asm volatile(
        "mma.sync.aligned.m16n8k8.row.col.f32.tf32.tf32.f32 "
        "{%0,%1,%2,%3}, {%4,%5,%6,%7}, {%8,%9}, {%0,%1,%2,%3};\n"
        : "+f"(d[0]), "+f"(d[1]), "+f"(d[2]), "+f"(d[3])
        : "r"(a[0]), "r"(a[1]), "r"(a[2]), "r"(a[3]), "r"(b[0]), "r"(b[1]));
}

// ---------------- 1) all projections (pos-add fused), ONE launch ----------------
__global__ void proj_all_kernel(const float* __restrict__ qx, const float* __restrict__ kvx,
                                const float* __restrict__ pos,
                                const float* __restrict__ Wq,  const float* __restrict__ bq,
                                const float* __restrict__ Wka, const float* __restrict__ bka,
                                const float* __restrict__ Wva, const float* __restrict__ bva,
                                const float* __restrict__ Wksa,const float* __restrict__ bksa,
                                const float* __restrict__ Wvsa,const float* __restrict__ bvsa) {
    int bx = blockIdx.x;
    const float *W, *bias, *x; float* dst; int N, n0, h0;
    bool isq = false;
    if (bx < 8)       { W=Wq;   bias=bq;   x=qx;  dst=g_q; N=512; n0=bx*64;      h0=0; isq=true; }
    else if (bx < 12) { W=Wka;  bias=bka;  x=kvx; dst=g_k; N=256; n0=(bx-8)*64;  h0=0; }
    else if (bx < 16) { W=Wksa; bias=bksa; x=qx;  dst=g_k; N=256; n0=(bx-12)*64; h0=4; }
    else if (bx < 20) { W=Wva;  bias=bva;  x=kvx; dst=g_v; N=256; n0=(bx-16)*64; h0=0; }
    else              { W=Wvsa; bias=bvsa; x=qx;  dst=g_v; N=256; n0=(bx-20)*64; h0=4; }

    __shared__ float As[64][65];
    __shared__ float Ws[64][65];
    int tid = threadIdx.x;
    int tx = tid & 15, ty = tid >> 4;
    int m0 = blockIdx.y * 64;

    #pragma unroll
    for (int e = 0; e < 16; e++) {
        int idx = e * 256 + tid;
        int r = idx >> 6, c = idx & 63;
        int s = (m0 + r) & 1023;
        As[r][c] = x[(size_t)(m0 + r) * 64 + c] + pos[s * 64 + c];
        Ws[r][c] = W[r * N + n0 + c];
    }
    __syncthreads();

    float acc[4][4];
    #pragma unroll
    for (int ci = 0; ci < 4; ci++) {
        float bv = bias[n0 + tx + 16 * ci];
        #pragma unroll
        for (int ri = 0; ri < 4; ri++) acc[ri][ci] = bv;
    }
    #pragma unroll
    for (int k = 0; k < 64; k++) {
        float a[4], b2[4];
        #pragma unroll
        for (int ri = 0; ri < 4; ri++) a[ri]  = As[ty + 16 * ri][k];
        #pragma unroll
        for (int ci = 0; ci < 4; ci++) b2[ci] = Ws[k][tx + 16 * ci];
        #pragma unroll
        for (int ri = 0; ri < 4; ri++)
            #pragma unroll
            for (int ci = 0; ci < 4; ci++)
                acc[ri][ci] += a[ri] * b2[ci];
    }
    float qs = isq ? 0.125f : 1.0f;   // exact pow2: folds score scale into q
    #pragma unroll
    for (int ri = 0; ri < 4; ri++)
        #pragma unroll
        for (int ci = 0; ci < 4; ci++) {
            int m = m0 + ty + 16 * ri;
            int n = n0 + tx + 16 * ci;
            int b = m >> 10, s = m & 1023;
            int h = n >> 6,  d = n & 63;
            dst[((size_t)(b * HEn + h0 + h) * Sn + s) * Dn + d] =
                __uint_as_float(f2tf(acc[ri][ci] * qs));
        }
}

// ---------------- 2) FUSED flash attention: scores+softmax+attn-write+ctx ----------------
// Block = 128 q-rows of one (b,h), 8 warps, warp = 16 rows (rows fully in-warp).
// Pass A: online max/sumexp over K chunks (64 cols).  Pass B: recompute S,
// P=exp(S-m)/l, write attn once, P@V into ctx accumulators.
#define KST 76   // stride for Q/K/P fragment buffers: bank = 12g+tig (conflict-free)
#define VST 72   // stride for V buffer: bank = 8tig+g (conflict-free)
__global__ void __launch_bounds__(256) flash_kernel(float* __restrict__ attn) {
    extern __shared__ unsigned sh[];
    unsigned* Qs = sh;               // [128][76]; reused as Ps in pass B
    unsigned* K0 = sh + 128 * KST;   // [64][76]
    unsigned* K1 = K0 + 64 * KST;    // [64][76]; pass A ping buffer, pass B V (stride 72)

    int bh = blockIdx.y;
    int m0 = blockIdx.x * 128;
    const float* __restrict__ qb = g_q + (size_t)bh * Sn * Dn;
    const float* __restrict__ kb = g_k + (size_t)bh * Sn * Dn;
    const float* __restrict__ vb = g_v + (size_t)bh * Sn * Dn;
    float* ab = attn + (size_t)bh * Sn * Sn;

    int tid = threadIdx.x, wid = tid >> 5, lane = tid & 31;
    int g = lane >> 2, tig = lane & 3;
    int qrow = wid * 16 + g;

    // ---- stage Q (128x64 tf32) ----
    #pragma unroll
    for (int e = 0; e < 8; e++) {
        int lin = e * 256 + tid;
        int r = lin >> 4, c4 = lin & 15;
        *(uint4*)&Qs[r * KST + c4 * 4] = *(const uint4*)&qb[(size_t)(m0 + r) * 64 + c4 * 4];
    }
    __syncthreads();
    unsigned aq[8][4];
    #pragma unroll
    for (int ks = 0; ks < 8; ks++) {
        int base = qrow * KST + ks * 8 + tig;
        aq[ks][0] = Qs[base];
        aq[ks][1] = Qs[base + 8 * KST];
        aq[ks][2] = Qs[base + 4];
        aq[ks][3] = Qs[base + 8 * KST + 4];
    }
    __syncthreads();

    float m_a = -1e30f, l_a = 0.f, m_b = -1e30f, l_b = 0.f;

    // ---- PASS A: online stats ----
    for (int kt = 0; kt < 16; kt++) {
        unsigned* Kc = (kt & 1) ? K1 : K0;
        #pragma unroll
        for (int e = 0; e < 4; e++) {
            int lin = e * 256 + tid;
            int r = lin >> 4, c4 = lin & 15;
            *(uint4*)&Kc[r * KST + c4 * 4] =
                *(const uint4*)&kb[(size_t)(kt * 64 + r) * 64 + c4 * 4];
        }
        __syncthreads();
        float sacc[8][4] = {};
        #pragma unroll
        for (int ks = 0; ks < 8; ks++)
            #pragma unroll
            for (int j = 0; j < 8; j++) {
                int br = (j * 8 + g) * KST + ks * 8 + tig;
                unsigned b2[2] = { Kc[br], Kc[br + 4] };
                mma8(sacc[j], aq[ks], b2);
            }
        // stats for row qrow (vals [0],[1]) and qrow+8 ([2],[3])
        float vm = -1e30f, wm = -1e30f;
        #pragma unroll
        for (int j = 0; j < 8; j++) {
            vm = fmaxf(vm, fmaxf(sacc[j][0], sacc[j][1]));
            wm = fmaxf(wm, fmaxf(sacc[j][2], sacc[j][3]));
        }
        vm = fmaxf(vm, __shfl_xor_sync(~0u, vm, 1));
        vm = fmaxf(vm, __shfl_xor_sync(~0u, vm, 2));
        wm = fmaxf(wm, __shfl_xor_sync(~0u, wm, 1));
        wm = fmaxf(wm, __shfl_xor_sync(~0u, wm, 2));
        float nma = fmaxf(m_a, vm), nmb = fmaxf(m_b, wm);
        float cs = 0.f, cs2 = 0.f;
        #pragma unroll
        for (int j = 0; j < 8; j++) {
            cs  += __expf(sacc[j][0] - nma) + __expf(sacc[j][1] - nma);
            cs2 += __expf(sacc[j][2] - nmb) + __expf(sacc[j][3] - nmb);
        }
        cs  += __shfl_xor_sync(~0u, cs, 1);  cs  += __shfl_xor_sync(~0u, cs, 2);
        cs2 += __shfl_xor_sync(~0u, cs2, 1); cs2 += __shfl_xor_sync(~0u, cs2, 2);
        l_a = l_a * __expf(m_a - nma) + cs;  m_a = nma;
        l_b = l_b * __expf(m_b - nmb) + cs2; m_b = nmb;
    }
    float il_a = 1.0f / l_a, il_b = 1.0f / l_b;

    // ---- PASS B: recompute S, P, attn write, ctx mma ----
    unsigned* Ps = Qs;
    float cacc[8][4] = {};
    for (int kt = 0; kt < 16; kt++) {
        __syncthreads();   // prev-iter fragment reads complete before overwrite
        #pragma unroll
        for (int e = 0; e < 4; e++) {
            int lin = e * 256 + tid;
            int r = lin >> 4, c4 = lin & 15;
            *(uint4*)&K0[r * KST + c4 * 4] =
                *(const uint4*)&kb[(size_t)(kt * 64 + r) * 64 + c4 * 4];
            *(uint4*)&K1[r * VST + c4 * 4] =
                *(const uint4*)&vb[(size_t)(kt * 64 + r) * 64 + c4 * 4];
        }
        __syncthreads();
        float sacc[8][4] = {};
        #pragma unroll
        for (int ks = 0; ks < 8; ks++)
            #pragma unroll
            for (int j = 0; j < 8; j++) {
                int br = (j * 8 + g) * KST + ks * 8 + tig;
                unsigned b2[2] = { K0[br], K0[br + 4] };
                mma8(sacc[j], aq[ks], b2);
            }
        #pragma unroll
        for (int j = 0; j < 8; j++) {
            float p0 = __expf(sacc[j][0] - m_a) * il_a;
            float p1 = __expf(sacc[j][1] - m_a) * il_a;
            float p2 = __expf(sacc[j][2] - m_b) * il_b;
            float p3 = __expf(sacc[j][3] - m_b) * il_b;
            int col = kt * 64 + j * 8 + 2 * tig;
            *(float2*)&ab[(size_t)(m0 + qrow) * Sn + col]     = make_float2(p0, p1);
            *(float2*)&ab[(size_t)(m0 + qrow + 8) * Sn + col] = make_float2(p2, p3);
            uint2 u0 = { f2tf(p0), f2tf(p1) };
            uint2 u1 = { f2tf(p2), f2tf(p3) };
            *(uint2*)&Ps[qrow * KST + j * 8 + 2 * tig]       = u0;
            *(uint2*)&Ps[(qrow + 8) * KST + j * 8 + 2 * tig] = u1;
        }
        // own-warp STS->LDS: program order; Ps rows are private to this warp
        #pragma unroll
        for (int ks = 0; ks < 8; ks++) {
            unsigned ap[4];
            int base = qrow * KST + ks * 8 + tig;
            ap[0] = Ps[base];
            ap[1] = Ps[base + 8 * KST];
            ap[2] = Ps[base + 4];
            ap[3] = Ps[base + 8 * KST + 4];
            int c = ks * 8 + tig;
            #pragma unroll
            for (int j = 0; j < 8; j++) {
                unsigned bv[2] = { K1[c * VST + j * 8 + g], K1[(c + 4) * VST + j * 8 + g] };
                mma8(cacc[j], ap, bv);
            }
        }
    }

    // ---- write ctx (B,S,512) ----
    int b = bh >> 3, h = bh & 7;
    #pragma unroll
    for (int j = 0; j < 8; j++) {
        int s = m0 + qrow;
        int d = j * 8 + 2 * tig;
        *(float2*)&g_ctx[((size_t)(b * Sn + s)) * CW + h * 64 + d] =
            make_float2(cacc[j][0], cacc[j][1]);
        *(float2*)&g_ctx[((size_t)(b * Sn + s + 8)) * CW + h * 64 + d] =
            make_float2(cacc[j][2], cacc[j][3]);
    }
}
#define FLASH_SMEM ((128 * KST + 64 * KST + 64 * KST) * 4)

// ---------------- 3) out = ctx @ Wo + bo ----------------
__global__ void __launch_bounds__(256) outproj_kernel(const float* __restrict__ Wo,
                                                      const float* __restrict__ bo,
                                                      float* __restrict__ out) {
    __shared__ float As[16][36];
    __shared__ float Bs[32][68];
    int tid = threadIdx.x;
    int ty = tid >> 4, tx = tid & 15;
    int m0 = blockIdx.x * 16;

    float acc[4];
    #pragma unroll
    for (int c2 = 0; c2 < 4; c2++) acc[c2] = bo[tx * 4 + c2];

    for (int kt = 0; kt < CW; kt += 32) {
        {
            int r = tid >> 4, c = (tid & 15) * 2;
            *(float2*)&As[r][c] = *(const float2*)&g_ctx[(size_t)(m0 + r) * CW + kt + c];
        }
        #pragma unroll
        for (int e = 0; e < 2; e++) {
            int lin = e * 256 + tid;
            int r = lin >> 4, c4 = lin & 15;
            *(float4*)&Bs[r][c4 * 4] = *(const float4*)&Wo[(size_t)(kt + r) * 64 + c4 * 4];
        }
        __syncthreads();
        #pragma unroll
        for (int k = 0; k < 32; k++) {
            float a = As[ty][k];
            float4 bv = *(const float4*)&Bs[k][tx * 4];
            acc[0] += a * bv.x; acc[1] += a * bv.y;
            acc[2] += a * bv.z; acc[3] += a * bv.w;
        }
        __syncthreads();
    }
    *(float4*)&out[(size_t)(m0 + ty) * 64 + tx * 4] =
        make_float4(acc[0], acc[1], acc[2], acc[3]);
}

// ---------------- launch ----------------
extern "C" void kernel_launch(void* const* d_in, const int* in_sizes, int n_in,
                              void* d_out, int out_size) {
    const float* kvx  = (const float*)d_in[0];
    const float* qx   = (const float*)d_in[1];
    const float* pos  = (const float*)d_in[2];
    const float* Wq   = (const float*)d_in[3];
    const float* bq   = (const float*)d_in[4];
    const float* Wka  = (const float*)d_in[5];
    const float* bka  = (const float*)d_in[6];
    const float* Wva  = (const float*)d_in[7];
    const float* bva  = (const float*)d_in[8];
    const float* Wksa = (const float*)d_in[9];
    const float* bksa = (const float*)d_in[10];
    const float* Wvsa = (const float*)d_in[11];
    const float* bvsa = (const float*)d_in[12];
    const float* Wo   = (const float*)d_in[13];
    const float* bo   = (const float*)d_in[14];

    float* out  = (float*)d_out;
    float* attn = out + (size_t)Bn * Sn * Dn;

    static bool attr_set = false;
    if (!attr_set) {
        cudaFuncSetAttribute(flash_kernel,
                             cudaFuncAttributeMaxDynamicSharedMemorySize, FLASH_SMEM);
        attr_set = true;
    }

    proj_all_kernel<<<dim3(24, BSn/64), 256>>>(qx, kvx, pos, Wq, bq, Wka, bka,
                                               Wva, bva, Wksa, bksa, Wvsa, bvsa);
    flash_kernel<<<dim3(Sn/128, Bn*HEn), 256, FLASH_SMEM>>>(attn);
    outproj_kernel<<<BSn/16, 256>>>(Wo, bo, out);
}

// round 9
// speedup vs baseline: 3.2125x; 1.9005x over previous
#include <cuda_runtime.h>
#include <cuda_fp16.h>
#include <math.h>

#define Bn   8
#define Sn   1024
#define Dn   64
#define NHn  4
#define HEn  8            // 2*NH
#define BSn  (Bn*Sn)      // 8192
#define CW   (HEn*Dn)     // 512

// ---------------- scratch (no allocation allowed) ----------------
__device__ __align__(16) __half g_qh [Bn*HEn*Sn*Dn];  // (B,8,S,D) fp16, pre-scaled 1/8
__device__ __align__(16) __half g_kh [Bn*HEn*Sn*Dn];  // (B,8,S,D) fp16
__device__ __align__(16) __half g_vt [Bn*HEn*Dn*Sn];  // (B,8,D,S) fp16 TRANSPOSED
__device__ float g_ctx [Bn*Sn*CW];                    // (B,S,512) fp32

// ---------------- helpers ----------------
__device__ __forceinline__ unsigned packh2(float a, float b) {
    __half2 h = __floats2half2_rn(a, b);
    return *reinterpret_cast<unsigned*>(&h);
}

__device__ __forceinline__ void mma16(float* d, const unsigned* a, const unsigned* b) {
    asm volatile(
        "mma.sync.aligned.m16n8k16.row.col.f32.f16.f16.f32 "
        "{%0,%1,%2,%3}, {%4,%5,%6,%7}, {%8,%9}, {%0,%1,%2,%3};\n"
        : "+f"(d[0]), "+f"(d[1]), "+f"(d[2]), "+f"(d[3])
        : "r"(a[0]), "r"(a[1]), "r"(a[2]), "r"(a[3]), "r"(b[0]), "r"(b[1]));
}

// ---------------- 1) all projections as fp16 mma (pos-add fused) ----------------
// Block = 128 rows x 64 cols of one target matrix. 8 warps, warp = 16 rows.
__global__ void __launch_bounds__(256) proj_all_kernel(
        const float* __restrict__ qx, const float* __restrict__ kvx,
        const float* __restrict__ pos,
        const float* __restrict__ Wq,  const float* __restrict__ bq,
        const float* __restrict__ Wka, const float* __restrict__ bka,
        const float* __restrict__ Wva, const float* __restrict__ bva,
        const float* __restrict__ Wksa,const float* __restrict__ bksa,
        const float* __restrict__ Wvsa,const float* __restrict__ bvsa) {
    int bx = blockIdx.x;
    const float *W, *bias, *x; int N, n0, h0, kind; // kind 0=q,1=k,2=v
    if (bx < 8)       { W=Wq;   bias=bq;   x=qx;  N=512; n0=bx*64;      h0=0; kind=0; }
    else if (bx < 12) { W=Wka;  bias=bka;  x=kvx; N=256; n0=(bx-8)*64;  h0=0; kind=1; }
    else if (bx < 16) { W=Wksa; bias=bksa; x=qx;  N=256; n0=(bx-12)*64; h0=4; kind=1; }
    else if (bx < 20) { W=Wva;  bias=bva;  x=kvx; N=256; n0=(bx-16)*64; h0=0; kind=2; }
    else              { W=Wvsa; bias=bvsa; x=qx;  N=256; n0=(bx-20)*64; h0=4; kind=2; }

    __shared__ unsigned Xs[128 * 36];  // [128 rows][72 halves]
    __shared__ unsigned Wt[64 * 36];   // [64 n][72 halves] (W transposed)
    __half* Wh = (__half*)Wt;

    int tid = threadIdx.x, wid = tid >> 5, lane = tid & 31;
    int g = lane >> 2, tig = lane & 3;
    int m0 = blockIdx.y * 128;

    // stage X + pos as fp16
    #pragma unroll
    for (int e = 0; e < 8; e++) {
        int lin = e * 256 + tid;
        int r = lin >> 4, c4 = lin & 15;
        float4 xv = *(const float4*)&x[(size_t)(m0 + r) * 64 + c4 * 4];
        float4 pv = *(const float4*)&pos[(size_t)((m0 + r) & 1023) * 64 + c4 * 4];
        uint2 u = { packh2(xv.x + pv.x, xv.y + pv.y),
                    packh2(xv.z + pv.z, xv.w + pv.w) };
        *(uint2*)&Xs[r * 36 + c4 * 2] = u;
    }
    // stage W transposed [n][k]
    #pragma unroll
    for (int e = 0; e < 4; e++) {
        int lin = e * 256 + tid;
        int k = lin >> 4, c4 = lin & 15;
        float4 wv = *(const float4*)&W[(size_t)k * N + n0 + c4 * 4];
        Wh[(c4 * 4 + 0) * 72 + k] = __float2half_rn(wv.x);
        Wh[(c4 * 4 + 1) * 72 + k] = __float2half_rn(wv.y);
        Wh[(c4 * 4 + 2) * 72 + k] = __float2half_rn(wv.z);
        Wh[(c4 * 4 + 3) * 72 + k] = __float2half_rn(wv.w);
    }
    __syncthreads();

    float acc[8][4];
    #pragma unroll
    for (int j = 0; j < 8; j++) {
        float2 bv = *(const float2*)&bias[n0 + j * 8 + 2 * tig];
        acc[j][0] = bv.x; acc[j][1] = bv.y; acc[j][2] = bv.x; acc[j][3] = bv.y;
    }
    #pragma unroll
    for (int ks = 0; ks < 4; ks++) {
        int base = (wid * 16 + g) * 36 + ks * 8 + tig;
        unsigned a[4] = { Xs[base], Xs[base + 8 * 36], Xs[base + 4], Xs[base + 8 * 36 + 4] };
        #pragma unroll
        for (int j = 0; j < 8; j++) {
            int bw = (j * 8 + g) * 36 + ks * 8 + tig;
            unsigned b2[2] = { Wt[bw], Wt[bw + 4] };
            mma16(acc[j], a, b2);
        }
    }
    float sc = (kind == 0) ? 0.125f : 1.0f;
    int m = m0 + wid * 16 + g;
    int b = m >> 10, s = m & 1023;
    #pragma unroll
    for (int j = 0; j < 8; j++) {
        int n = n0 + j * 8 + 2 * tig;
        int h = n >> 6, d = n & 63;
        #pragma unroll
        for (int rh = 0; rh < 2; rh++) {
            float v0 = acc[j][rh * 2] * sc, v1 = acc[j][rh * 2 + 1] * sc;
            int srow = s + rh * 8;
            if (kind == 2) {
                size_t base2 = ((size_t)(b * HEn + h0 + h) * Dn + d) * Sn + srow;
                g_vt[base2]      = __float2half_rn(v0);
                g_vt[base2 + Sn] = __float2half_rn(v1);
            } else {
                __half* dst = (kind == 0) ? g_qh : g_kh;
                size_t idx = ((size_t)(b * HEn + h0 + h) * Sn + srow) * Dn + d;
                *(unsigned*)&dst[idx] = packh2(v0, v1);
            }
        }
    }
}

// ---------------- 2) FUSED flash attention (fp16 mma) ----------------
// Block = 128 q-rows of one (b,h), 8 warps, warp = 16 rows.
// Pass A: online max/sumexp. Pass B: recompute S, write attn, P@V (P from regs).
__global__ void __launch_bounds__(256) flash_kernel(float* __restrict__ attn) {
    __shared__ unsigned sh[(128 + 64 + 64) * 36];
    unsigned* Qs  = sh;              // [128][72h]; pass B: ping buffers 1
    unsigned* K0s = sh + 128 * 36;   // [64][72h]
    unsigned* K1s = K0s + 64 * 36;   // [64][72h]

    int bh = blockIdx.y;
    int m0 = blockIdx.x * 128;
    const __half* qb = g_qh + (size_t)bh * Sn * Dn;
    const __half* kb = g_kh + (size_t)bh * Sn * Dn;
    const __half* vb = g_vt + (size_t)bh * Dn * Sn;   // [64 d][1024 s]
    float* ab = attn + (size_t)bh * Sn * Sn;

    int tid = threadIdx.x, wid = tid >> 5, lane = tid & 31;
    int g = lane >> 2, tig = lane & 3;
    int qrow = wid * 16 + g;

    // ---- stage Q (128x64 fp16) ----
    #pragma unroll
    for (int e = 0; e < 4; e++) {
        int lin = e * 256 + tid;
        int r = lin >> 3, c8 = lin & 7;
        *(uint4*)&Qs[r * 36 + c8 * 4] = ((const uint4*)qb)[(size_t)(m0 + r) * 8 + c8];
    }
    __syncthreads();
    unsigned aq[4][4];
    #pragma unroll
    for (int ks = 0; ks < 4; ks++) {
        int base = qrow * 36 + ks * 8 + tig;
        aq[ks][0] = Qs[base];
        aq[ks][1] = Qs[base + 8 * 36];
        aq[ks][2] = Qs[base + 4];
        aq[ks][3] = Qs[base + 8 * 36 + 4];
    }
    __syncthreads();

    float m_a = -1e30f, l_a = 0.f, m_b = -1e30f, l_b = 0.f;

    // ---- PASS A: online stats, K ping-pong, 1 sync/iter ----
    for (int kt = 0; kt < 16; kt++) {
        unsigned* Kc = (kt & 1) ? K1s : K0s;
        #pragma unroll
        for (int e = 0; e < 2; e++) {
            int lin = e * 256 + tid;
            int r = lin >> 3, c8 = lin & 7;
            *(uint4*)&Kc[r * 36 + c8 * 4] = ((const uint4*)kb)[(size_t)(kt * 64 + r) * 8 + c8];
        }
        __syncthreads();
        float sacc[8][4] = {};
        #pragma unroll
        for (int ks = 0; ks < 4; ks++)
            #pragma unroll
            for (int j = 0; j < 8; j++) {
                int bw = (j * 8 + g) * 36 + ks * 8 + tig;
                unsigned b2[2] = { Kc[bw], Kc[bw + 4] };
                mma16(sacc[j], aq[ks], b2);
            }
        float vm = -1e30f, wm = -1e30f;
        #pragma unroll
        for (int j = 0; j < 8; j++) {
            vm = fmaxf(vm, fmaxf(sacc[j][0], sacc[j][1]));
            wm = fmaxf(wm, fmaxf(sacc[j][2], sacc[j][3]));
        }
        vm = fmaxf(vm, __shfl_xor_sync(~0u, vm, 1));
        vm = fmaxf(vm, __shfl_xor_sync(~0u, vm, 2));
        wm = fmaxf(wm, __shfl_xor_sync(~0u, wm, 1));
        wm = fmaxf(wm, __shfl_xor_sync(~0u, wm, 2));
        float nma = fmaxf(m_a, vm), nmb = fmaxf(m_b, wm);
        float cs = 0.f, cs2 = 0.f;
        #pragma unroll
        for (int j = 0; j < 8; j++) {
            cs  += __expf(sacc[j][0] - nma) + __expf(sacc[j][1] - nma);
            cs2 += __expf(sacc[j][2] - nmb) + __expf(sacc[j][3] - nmb);
        }
        cs  += __shfl_xor_sync(~0u, cs, 1);  cs  += __shfl_xor_sync(~0u, cs, 2);
        cs2 += __shfl_xor_sync(~0u, cs2, 1); cs2 += __shfl_xor_sync(~0u, cs2, 2);
        l_a = l_a * __expf(m_a - nma) + cs;  m_a = nma;
        l_b = l_b * __expf(m_b - nmb) + cs2; m_b = nmb;
    }
    float il_a = 1.0f / l_a, il_b = 1.0f / l_b;
    __syncthreads();   // pass A readers done before pass B overwrites buffers

    // ---- PASS B: recompute S, attn write, ctx mma; (K,V) pair ping-pong ----
    float cacc[8][4] = {};
    for (int kt = 0; kt < 16; kt++) {
        unsigned* Kc = (kt & 1) ? Qs : K0s;
        unsigned* Vc = (kt & 1) ? (Qs + 64 * 36) : K1s;
        #pragma unroll
        for (int e = 0; e < 2; e++) {
            int lin = e * 256 + tid;
            int r = lin >> 3, c8 = lin & 7;
            *(uint4*)&Kc[r * 36 + c8 * 4] = ((const uint4*)kb)[(size_t)(kt * 64 + r) * 8 + c8];
            // V transposed: row = d, cols = s chunk
            *(uint4*)&Vc[r * 36 + c8 * 4] = ((const uint4*)vb)[(size_t)r * 128 + kt * 8 + c8];
        }
        __syncthreads();
        float sacc[8][4] = {};
        #pragma unroll
        for (int ks = 0; ks < 4; ks++)
            #pragma unroll
            for (int j = 0; j < 8; j++) {
                int bw = (j * 8 + g) * 36 + ks * 8 + tig;
                unsigned b2[2] = { Kc[bw], Kc[bw + 4] };
                mma16(sacc[j], aq[ks], b2);
            }
        unsigned ph[8][2];   // ph[j] = {h2(p0,p1), h2(p2,p3)}
        #pragma unroll
        for (int j = 0; j < 8; j++) {
            float p0 = __expf(sacc[j][0] - m_a) * il_a;
            float p1 = __expf(sacc[j][1] - m_a) * il_a;
            float p2 = __expf(sacc[j][2] - m_b) * il_b;
            float p3 = __expf(sacc[j][3] - m_b) * il_b;
            int col = kt * 64 + j * 8 + 2 * tig;
            *(float2*)&ab[(size_t)(m0 + qrow) * Sn + col]     = make_float2(p0, p1);
            *(float2*)&ab[(size_t)(m0 + qrow + 8) * Sn + col] = make_float2(p2, p3);
            ph[j][0] = packh2(p0, p1);
            ph[j][1] = packh2(p2, p3);
        }
        // ctx mma: A-fragments directly from ph (no smem round-trip)
        #pragma unroll
        for (int ks2 = 0; ks2 < 4; ks2++) {
            unsigned ap[4] = { ph[2 * ks2][0], ph[2 * ks2][1],
                               ph[2 * ks2 + 1][0], ph[2 * ks2 + 1][1] };
            #pragma unroll
            for (int j = 0; j < 8; j++) {
                int bw = (j * 8 + g) * 36 + ks2 * 8 + tig;
                unsigned bv[2] = { Vc[bw], Vc[bw + 4] };
                mma16(cacc[j], ap, bv);
            }
        }
    }

    // ---- write ctx (B,S,512) fp32 ----
    int b = bh >> 3, h = bh & 7;
    #pragma unroll
    for (int j = 0; j < 8; j++) {
        int s = m0 + qrow;
        int d = j * 8 + 2 * tig;
        *(float2*)&g_ctx[((size_t)(b * Sn + s)) * CW + h * 64 + d] =
            make_float2(cacc[j][0], cacc[j][1]);
        *(float2*)&g_ctx[((size_t)(b * Sn + s + 8)) * CW + h * 64 + d] =
            make_float2(cacc[j][2], cacc[j][3]);
    }
}

// ---------------- 3) out = ctx @ Wo + bo ----------------
__global__ void __launch_bounds__(256) outproj_kernel(const float* __restrict__ Wo,
                                                      const float* __restrict__ bo,
                                                      float* __restrict__ out) {
    __shared__ float As[16][36];
    __shared__ float Bs[32][68];
    int tid = threadIdx.x;
    int ty = tid >> 4, tx = tid & 15;
    int m0 = blockIdx.x * 16;

    float acc[4];
    #pragma unroll
    for (int c2 = 0; c2 < 4; c2++) acc[c2] = bo[tx * 4 + c2];

    for (int kt = 0; kt < CW; kt += 32) {
        {
            int r = tid >> 4, c = (tid & 15) * 2;
            *(float2*)&As[r][c] = *(const float2*)&g_ctx[(size_t)(m0 + r) * CW + kt + c];
        }
        #pragma unroll
        for (int e = 0; e < 2; e++) {
            int lin = e * 256 + tid;
            int r = lin >> 4, c4 = lin & 15;
            *(float4*)&Bs[r][c4 * 4] = *(const float4*)&Wo[(size_t)(kt + r) * 64 + c4 * 4];
        }
        __syncthreads();
        #pragma unroll
        for (int k = 0; k < 32; k++) {
            float a = As[ty][k];
            float4 bv = *(const float4*)&Bs[k][tx * 4];
            acc[0] += a * bv.x; acc[1] += a * bv.y;
            acc[2] += a * bv.z; acc[3] += a * bv.w;
        }
        __syncthreads();
    }
    *(float4*)&out[(size_t)(m0 + ty) * 64 + tx * 4] =
        make_float4(acc[0], acc[1], acc[2], acc[3]);
}

// ---------------- launch ----------------
extern "C" void kernel_launch(void* const* d_in, const int* in_sizes, int n_in,
                              void* d_out, int out_size) {
    const float* kvx  = (const float*)d_in[0];
    const float* qx   = (const float*)d_in[1];
    const float* pos  = (const float*)d_in[2];
    const float* Wq   = (const float*)d_in[3];
    const float* bq   = (const float*)d_in[4];
    const float* Wka  = (const float*)d_in[5];
    const float* bka  = (const float*)d_in[6];
    const float* Wva  = (const float*)d_in[7];
    const float* bva  = (const float*)d_in[8];
    const float* Wksa = (const float*)d_in[9];
    const float* bksa = (const float*)d_in[10];
    const float* Wvsa = (const float*)d_in[11];
    const float* bvsa = (const float*)d_in[12];
    const float* Wo   = (const float*)d_in[13];
    const float* bo   = (const float*)d_in[14];

    float* out  = (float*)d_out;
    float* attn = out + (size_t)Bn * Sn * Dn;

    proj_all_kernel<<<dim3(24, BSn/128), 256>>>(qx, kvx, pos, Wq, bq, Wka, bka,
                                                Wva, bva, Wksa, bksa, Wvsa, bvsa);
    flash_kernel<<<dim3(Sn/128, Bn*HEn), 256>>>(attn);
    outproj_kernel<<<BSn/16, 256>>>(Wo, bo, out);
}